// round 3
// baseline (speedup 1.0000x reference)
#include <cuda_runtime.h>
#include <cstdint>

#define ENT_NUM 100000
#define REL_NUM 500
#define DIM     128
#define BATCH   16384
#define ALPHA   0.001f
#define NHBLK   8          // histogram / scatter blocks

// ---- device scratch (no allocations allowed) ----
__device__ int   g_counts_part[NHBLK * 512];
__device__ int   g_offsets[REL_NUM + 1];
__device__ int   g_fill[512];
__device__ int   g_perm[BATCH];
__device__ float g_part_h2[REL_NUM];
__device__ float g_part_t2[REL_NUM];
__device__ float g_part_r2[REL_NUM];

// ---------------------------------------------------------------------------
// packed f32x2 helpers (sm_100+)
// ---------------------------------------------------------------------------
__device__ __forceinline__ unsigned long long ffma2(unsigned long long a,
                                                    unsigned long long b,
                                                    unsigned long long c) {
    asm("fma.rn.f32x2 %0, %1, %2, %0;" : "+l"(c) : "l"(a), "l"(b));
    return c;
}
__device__ __forceinline__ unsigned long long pk2(float x, float y) {
    unsigned long long r;
    asm("mov.b64 %0, {%1, %2};" : "=l"(r) : "f"(x), "f"(y));
    return r;
}
__device__ __forceinline__ float2 unpk2(unsigned long long v) {
    float2 r;
    asm("mov.b64 {%0, %1}, %2;" : "=f"(r.x), "=f"(r.y) : "l"(v));
    return r;
}

// ---------------------------------------------------------------------------
// Kernel A: privatized histogram (per-block smem) + zero the output buffer
// ---------------------------------------------------------------------------
__global__ __launch_bounds__(1024) void hist_kernel(
    const int* __restrict__ r_idx, float* __restrict__ out)
{
    __shared__ int hist[512];
    const int tid = threadIdx.x;
    const int blk = blockIdx.x;
    if (tid < 512) hist[tid] = 0;
    __syncthreads();

    const int base = blk * 2048;
    int r0 = r_idx[base + tid];
    int r1 = r_idx[base + 1024 + tid];
    atomicAdd(&hist[r0], 1);
    atomicAdd(&hist[r1], 1);

    // zero scores (REDG accumulation target)
    out[base + tid]        = 0.f;
    out[base + 1024 + tid] = 0.f;
    if (blk == 0 && tid == 0) out[BATCH] = 0.f;   // out has BATCH+1 elems

    __syncthreads();
    if (tid < 512) g_counts_part[blk * 512 + tid] = hist[tid];
}

// ---------------------------------------------------------------------------
// Kernel B: sum part-counts + inclusive scan (1 block, 512 threads)
// ---------------------------------------------------------------------------
__global__ __launch_bounds__(512) void scan_kernel() {
    __shared__ int s[512];
    const int tid = threadIdx.x;
    int v = 0;
    #pragma unroll
    for (int p = 0; p < NHBLK; p++) v += g_counts_part[p * 512 + tid];
    s[tid] = v;
    __syncthreads();
    for (int o = 1; o < 512; o <<= 1) {
        int add = (tid >= o) ? s[tid - o] : 0;
        __syncthreads();
        s[tid] += add;
        __syncthreads();
    }
    if (tid < REL_NUM) g_offsets[tid + 1] = s[tid];
    g_fill[tid] = s[tid] - v;      // exclusive prefix
    if (tid == 0) g_offsets[0] = 0;
}

// ---------------------------------------------------------------------------
// Kernel C: scatter batch ids into relation-grouped order
// ---------------------------------------------------------------------------
__global__ __launch_bounds__(1024) void scatter_kernel(
    const int* __restrict__ r_idx)
{
    const int b0 = blockIdx.x * 2048 + threadIdx.x;
    const int b1 = b0 + 1024;
    int p0 = atomicAdd(&g_fill[r_idx[b0]], 1);
    g_perm[p0] = b0;
    int p1 = atomicAdd(&g_fill[r_idx[b1]], 1);
    g_perm[p1] = b1;
}

// ---------------------------------------------------------------------------
// Main kernel: one CTA per relation. Each thread keeps a 64-float half-row
// of R in registers (32 packed f32x2). 4 batch elements per iteration,
// double-buffered staging (ONE __syncthreads per iteration), per-warp shfl
// reduce + no-return atomicAdd for scores.
// ---------------------------------------------------------------------------
__global__ __launch_bounds__(256, 2) void rescal_main_kernel(
    const int*   __restrict__ h_idx,
    const int*   __restrict__ t_idx,
    const float* __restrict__ ent_w,
    const float* __restrict__ rel_w,
    float*       __restrict__ out)     // out[0]=loss, out[1+b]=scores (pre-zeroed)
{
    __shared__ __align__(16) float t_sm[2][4][DIM];
    __shared__ float h_sm[2][4][DIM];
    __shared__ int   bs_sm[2][4];
    __shared__ float red2[8][3];

    const int r    = blockIdx.x;
    const int tid  = threadIdx.x;
    const int li   = tid & 127;        // row index
    const int ch   = tid >> 7;         // column half
    const int warp = tid >> 5;
    const int lane = tid & 31;

    // ---- load half-row of R into registers + Frobenius partial ----
    const float4* Rg = reinterpret_cast<const float4*>(
        rel_w + (size_t)r * (DIM * DIM) + (size_t)li * DIM + ch * 64);
    unsigned long long Rlo[16], Rhi[16];
    float ss = 0.f;
    #pragma unroll
    for (int k = 0; k < 16; k++) {
        float4 v = Rg[k];
        ss += v.x * v.x + v.y * v.y + v.z * v.z + v.w * v.w;
        Rlo[k] = pk2(v.x, v.y);
        Rhi[k] = pk2(v.z, v.w);
    }

    const int start = g_offsets[r];
    const int n     = g_offsets[r + 1] - start;

    // ---- prefetch iteration 0 (this thread stages elements ch and ch+2) ----
    float pt0 = 0.f, pt1 = 0.f, ph0 = 0.f, ph1 = 0.f;
    int pb0 = (ch < n)     ? g_perm[start + ch]     : -1;
    int pb1 = (ch + 2 < n) ? g_perm[start + ch + 2] : -1;
    if (pb0 >= 0) {
        pt0 = ent_w[(size_t)t_idx[pb0] * DIM + li];
        ph0 = ent_w[(size_t)h_idx[pb0] * DIM + li];
    }
    if (pb1 >= 0) {
        pt1 = ent_w[(size_t)t_idx[pb1] * DIM + li];
        ph1 = ent_w[(size_t)h_idx[pb1] * DIM + li];
    }

    float hh = 0.f, tt = 0.f;
    int buf = 0;

    for (int base = 0; base < n; base += 4, buf ^= 1) {
        // stage current iteration into buffer `buf`
        t_sm[buf][ch][li]     = pt0;
        t_sm[buf][ch + 2][li] = pt1;
        h_sm[buf][ch][li]     = ph0;
        h_sm[buf][ch + 2][li] = ph1;
        if (li == 0) { bs_sm[buf][ch] = pb0; bs_sm[buf][ch + 2] = pb1; }
        hh += ph0 * ph0 + ph1 * ph1;
        tt += pt0 * pt0 + pt1 * pt1;

        // prefetch next iteration (independent; hides under compute)
        {
            int nb = base + 4;
            pb0 = (nb + ch < n)     ? g_perm[start + nb + ch]     : -1;
            pb1 = (nb + ch + 2 < n) ? g_perm[start + nb + ch + 2] : -1;
            pt0 = pt1 = ph0 = ph1 = 0.f;
            if (pb0 >= 0) {
                pt0 = ent_w[(size_t)t_idx[pb0] * DIM + li];
                ph0 = ent_w[(size_t)h_idx[pb0] * DIM + li];
            }
            if (pb1 >= 0) {
                pt1 = ent_w[(size_t)t_idx[pb1] * DIM + li];
                ph1 = ent_w[(size_t)h_idx[pb1] * DIM + li];
            }
        }
        __syncthreads();               // staged buf visible; prev-prev readers done

        // ---- 4 matvec partials from register-resident R ----
        unsigned long long alo[4] = {0ull, 0ull, 0ull, 0ull};
        unsigned long long ahi[4] = {0ull, 0ull, 0ull, 0ull};
        #pragma unroll
        for (int k = 0; k < 16; k++) {
            #pragma unroll
            for (int e = 0; e < 4; e++) {
                ulonglong2 tv = *reinterpret_cast<const ulonglong2*>(
                    &t_sm[buf][e][ch * 64 + k * 4]);   // LDS.128 broadcast
                alo[e] = ffma2(Rlo[k], tv.x, alo[e]);
                ahi[e] = ffma2(Rhi[k], tv.y, ahi[e]);
            }
        }

        #pragma unroll
        for (int e = 0; e < 4; e++) {
            float2 lo = unpk2(alo[e]);
            float2 hi = unpk2(ahi[e]);
            float p = (lo.x + lo.y) + (hi.x + hi.y);
            float v = h_sm[buf][e][li] * p;
            #pragma unroll
            for (int o = 16; o; o >>= 1)
                v += __shfl_xor_sync(0xffffffffu, v, o);
            if (lane == 0) {
                int b = bs_sm[buf][e];
                if (b >= 0) atomicAdd(&out[1 + b], v);   // REDG, no return
            }
        }
    }

    // ---- final block reductions: hh, tt, ss ----
    #pragma unroll
    for (int o = 16; o; o >>= 1) {
        hh += __shfl_xor_sync(0xffffffffu, hh, o);
        tt += __shfl_xor_sync(0xffffffffu, tt, o);
        ss += __shfl_xor_sync(0xffffffffu, ss, o);
    }
    if (lane == 0) { red2[warp][0] = hh; red2[warp][1] = tt; red2[warp][2] = ss; }
    __syncthreads();
    if (tid == 0) {
        float HH = 0.f, TT = 0.f, SS = 0.f;
        #pragma unroll
        for (int w = 0; w < 8; w++) {
            HH += red2[w][0]; TT += red2[w][1]; SS += red2[w][2];
        }
        g_part_h2[r] = HH;
        g_part_t2[r] = TT;
        g_part_r2[r] = SS * (float)n;
    }
}

// ---------------------------------------------------------------------------
__global__ void finalize_kernel(const float* __restrict__ labels,
                                float* __restrict__ out) {
    __shared__ float sred[16 * 4];
    int tid = threadIdx.x;    // 512 threads
    float sq = 0.f;
    for (int b = tid; b < BATCH; b += 512) {
        float d = out[1 + b] - labels[b];
        sq += d * d;
    }
    float h2 = 0.f, t2 = 0.f, r2 = 0.f;
    for (int r = tid; r < REL_NUM; r += 512) {
        h2 += g_part_h2[r];
        t2 += g_part_t2[r];
        r2 += g_part_r2[r];
    }
    #pragma unroll
    for (int o = 16; o; o >>= 1) {
        sq += __shfl_xor_sync(0xffffffffu, sq, o);
        h2 += __shfl_xor_sync(0xffffffffu, h2, o);
        t2 += __shfl_xor_sync(0xffffffffu, t2, o);
        r2 += __shfl_xor_sync(0xffffffffu, r2, o);
    }
    int warp = tid >> 5, lane = tid & 31;
    if (lane == 0) {
        sred[warp * 4 + 0] = sq;
        sred[warp * 4 + 1] = h2;
        sred[warp * 4 + 2] = t2;
        sred[warp * 4 + 3] = r2;
    }
    __syncthreads();
    if (tid == 0) {
        float SQ = 0.f, H2 = 0.f, T2 = 0.f, R2 = 0.f;
        #pragma unroll
        for (int w = 0; w < 16; w++) {
            SQ += sred[w * 4 + 0];
            H2 += sred[w * 4 + 1];
            T2 += sred[w * 4 + 2];
            R2 += sred[w * 4 + 3];
        }
        float mh = H2 / ((float)BATCH * DIM);
        float mt = T2 / ((float)BATCH * DIM);
        float mr = R2 / ((float)BATCH * DIM * DIM);
        float norms = (mh + mt + mr) / 3.0f;
        out[0] = SQ / (float)BATCH + ALPHA * norms;
    }
}

// ---------------------------------------------------------------------------
extern "C" void kernel_launch(void* const* d_in, const int* in_sizes, int n_in,
                              void* d_out, int out_size) {
    const int*   h_idx  = (const int*)  d_in[0];
    const int*   r_idx  = (const int*)  d_in[1];
    const int*   t_idx  = (const int*)  d_in[2];
    const float* labels = (const float*)d_in[3];
    const float* ent_w  = (const float*)d_in[4];
    const float* rel_w  = (const float*)d_in[5];
    float* out = (float*)d_out;

    hist_kernel<<<NHBLK, 1024>>>(r_idx, out);
    scan_kernel<<<1, 512>>>();
    scatter_kernel<<<NHBLK, 1024>>>(r_idx);
    rescal_main_kernel<<<REL_NUM, 256>>>(h_idx, t_idx, ent_w, rel_w, out);
    finalize_kernel<<<1, 512>>>(labels, out);
}

// round 4
// speedup vs baseline: 1.1468x; 1.1468x over previous
#include <cuda_runtime.h>
#include <cstdint>

#define ENT_NUM 100000
#define REL_NUM 500
#define DIM     128
#define BATCH   16384
#define ALPHA   0.001f
#define NHBLK   8

// ---- device scratch (no allocations allowed) ----
__device__ int   g_counts_part[NHBLK * 512];
__device__ int   g_offsets[REL_NUM + 1];
__device__ int   g_fill[512];
__device__ int   g_perm[BATCH];
__device__ int   g_tidx_s[BATCH];
__device__ int   g_hidx_s[BATCH];
__device__ float g_part_h2[REL_NUM];
__device__ float g_part_t2[REL_NUM];
__device__ float g_part_r2[REL_NUM];

// ---------------------------------------------------------------------------
// packed f32x2 helpers (sm_100+)
// ---------------------------------------------------------------------------
typedef unsigned long long ull;
__device__ __forceinline__ ull ffma2(ull a, ull b, ull c) {
    ull d;
    asm("fma.rn.f32x2 %0, %1, %2, %3;" : "=l"(d) : "l"(a), "l"(b), "l"(c));
    return d;
}
__device__ __forceinline__ ull fmul2(ull a, ull b) {
    ull d;
    asm("mul.rn.f32x2 %0, %1, %2;" : "=l"(d) : "l"(a), "l"(b));
    return d;
}
__device__ __forceinline__ ull pk2(float x, float y) {
    ull r;
    asm("mov.b64 %0, {%1, %2};" : "=l"(r) : "f"(x), "f"(y));
    return r;
}
__device__ __forceinline__ float2 unpk2(ull v) {
    float2 r;
    asm("mov.b64 {%0, %1}, %2;" : "=f"(r.x), "=f"(r.y) : "l"(v));
    return r;
}

// ---------------------------------------------------------------------------
// Kernel A: privatized histogram + zero the output buffer
// ---------------------------------------------------------------------------
__global__ __launch_bounds__(1024) void hist_kernel(
    const int* __restrict__ r_idx, float* __restrict__ out)
{
    __shared__ int hist[512];
    const int tid = threadIdx.x;
    const int blk = blockIdx.x;
    if (tid < 512) hist[tid] = 0;
    __syncthreads();

    const int base = blk * 2048;
    int r0 = r_idx[base + tid];
    int r1 = r_idx[base + 1024 + tid];
    atomicAdd(&hist[r0], 1);
    atomicAdd(&hist[r1], 1);

    out[base + tid]        = 0.f;
    out[base + 1024 + tid] = 0.f;
    if (blk == 0 && tid == 0) out[BATCH] = 0.f;

    __syncthreads();
    if (tid < 512) g_counts_part[blk * 512 + tid] = hist[tid];
}

// ---------------------------------------------------------------------------
// Kernel B: sum part-counts + inclusive scan
// ---------------------------------------------------------------------------
__global__ __launch_bounds__(512) void scan_kernel() {
    __shared__ int s[512];
    const int tid = threadIdx.x;
    int v = 0;
    #pragma unroll
    for (int p = 0; p < NHBLK; p++) v += g_counts_part[p * 512 + tid];
    s[tid] = v;
    __syncthreads();
    for (int o = 1; o < 512; o <<= 1) {
        int add = (tid >= o) ? s[tid - o] : 0;
        __syncthreads();
        s[tid] += add;
        __syncthreads();
    }
    if (tid < REL_NUM) g_offsets[tid + 1] = s[tid];
    g_fill[tid] = s[tid] - v;
    if (tid == 0) g_offsets[0] = 0;
}

// ---------------------------------------------------------------------------
// Kernel C: scatter batch ids AND reordered entity indices
// ---------------------------------------------------------------------------
__global__ __launch_bounds__(1024) void scatter_kernel(
    const int* __restrict__ r_idx,
    const int* __restrict__ h_idx,
    const int* __restrict__ t_idx)
{
    const int b0 = blockIdx.x * 2048 + threadIdx.x;
    const int b1 = b0 + 1024;
    int p0 = atomicAdd(&g_fill[r_idx[b0]], 1);
    g_perm[p0]   = b0;
    g_tidx_s[p0] = t_idx[b0];
    g_hidx_s[p0] = h_idx[b0];
    int p1 = atomicAdd(&g_fill[r_idx[b1]], 1);
    g_perm[p1]   = b1;
    g_tidx_s[p1] = t_idx[b1];
    g_hidx_s[p1] = h_idx[b1];
}

// ---------------------------------------------------------------------------
// Main kernel: one CTA per relation.
// Thread (s = tid>>5, c = tid&31) owns R rows {s+8j, j=0..15} x cols [4c,4c+4).
// R loaded as flat coalesced float4 (f = tid + 256k -> row s+8k, cols 4c..).
// Per element: 1 t-LDS.128 feeds 32 ffma2; h pre-duplicated in smem so score
// weighting is 1 ffma2 per row. 8 elements per __syncthreads, group-ahead
// prefetch through reordered index arrays.
// ---------------------------------------------------------------------------
__global__ __launch_bounds__(256, 2) void rescal_main_kernel(
    const float* __restrict__ ent_w,
    const float* __restrict__ rel_w,
    float*       __restrict__ out)     // out[0]=loss, out[1+b]=scores (zeroed)
{
    __shared__ __align__(16) float  t_sm[2][8][DIM];
    __shared__ __align__(16) float2 hd_sm[2][8][8 * 17];  // [s*17+j], duplicated h
    __shared__ int   bs_sm[2][8];
    __shared__ float red2[8][3];

    const int r   = blockIdx.x;
    const int tid = threadIdx.x;
    const int s   = tid >> 5;          // warp id == row-set id
    const int c   = tid & 31;          // lane == column chunk

    // ---- coalesced R load: 16 float4, thread gets rows s+8k, cols 4c..4c+3 ----
    const float4* Rg4 = reinterpret_cast<const float4*>(
        rel_w + (size_t)r * (DIM * DIM));
    ull Rlo[16], Rhi[16];
    float ss = 0.f;
    #pragma unroll
    for (int k = 0; k < 16; k++) {
        float4 v = Rg4[tid + 256 * k];
        ss += v.x * v.x + v.y * v.y + v.z * v.z + v.w * v.w;
        Rlo[k] = pk2(v.x, v.y);
        Rhi[k] = pk2(v.z, v.w);
    }

    const int start = g_offsets[r];
    const int n     = g_offsets[r + 1] - start;
    const float4* entF4 = reinterpret_cast<const float4*>(ent_w);

    // ---- group-ahead prefetch registers (warp s stages element s of group) ----
    float4 pt4 = make_float4(0.f, 0.f, 0.f, 0.f);
    float4 ph4 = make_float4(0.f, 0.f, 0.f, 0.f);
    int pb = -1;
    {
        int idx = s;                    // group 0
        if (idx < n) {
            int pos = start + idx;
            pb = g_perm[pos];
            int tb = g_tidx_s[pos];
            int hb = g_hidx_s[pos];
            pt4 = entF4[(size_t)tb * 32 + c];
            ph4 = entF4[(size_t)hb * 32 + c];
        }
    }

    float hh = 0.f, tt = 0.f;
    const int ngrp = (n + 7) >> 3;
    int buf = 0;

    for (int grp = 0; grp < ngrp; grp++, buf ^= 1) {
        // ---- stage group into buffer ----
        *reinterpret_cast<float4*>(&t_sm[buf][s][c * 4]) = pt4;
        {
            const int j = c >> 1;
            const int sb = 4 * (c & 1);
            hd_sm[buf][s][(sb + 0) * 17 + j] = make_float2(ph4.x, ph4.x);
            hd_sm[buf][s][(sb + 1) * 17 + j] = make_float2(ph4.y, ph4.y);
            hd_sm[buf][s][(sb + 2) * 17 + j] = make_float2(ph4.z, ph4.z);
            hd_sm[buf][s][(sb + 3) * 17 + j] = make_float2(ph4.w, ph4.w);
        }
        if (c == 0) bs_sm[buf][s] = pb;
        hh += ph4.x * ph4.x + ph4.y * ph4.y + ph4.z * ph4.z + ph4.w * ph4.w;
        tt += pt4.x * pt4.x + pt4.y * pt4.y + pt4.z * pt4.z + pt4.w * pt4.w;

        // ---- prefetch next group (hidden under compute) ----
        {
            int idx = (grp + 1) * 8 + s;
            pb = -1;
            pt4 = make_float4(0.f, 0.f, 0.f, 0.f);
            ph4 = make_float4(0.f, 0.f, 0.f, 0.f);
            if (idx < n) {
                int pos = start + idx;
                pb = g_perm[pos];
                int tb = g_tidx_s[pos];
                int hb = g_hidx_s[pos];
                pt4 = entF4[(size_t)tb * 32 + c];
                ph4 = entF4[(size_t)hb * 32 + c];
            }
        }
        __syncthreads();               // staged buf visible to all

        // ---- compute 8 elements ----
        float sc[8];
        #pragma unroll
        for (int e = 0; e < 8; e++) {
            const ulonglong2 tvp = *reinterpret_cast<const ulonglong2*>(
                &t_sm[buf][e][c * 4]);                 // conflict-free LDS.128
            const ull* hdp = reinterpret_cast<const ull*>(
                &hd_sm[buf][e][s * 17]);               // LDS.64 broadcasts
            ull sc2 = 0ull;
            #pragma unroll
            for (int j = 0; j < 16; j++) {
                ull q = fmul2(Rlo[j], tvp.x);
                q = ffma2(Rhi[j], tvp.y, q);
                sc2 = ffma2(hdp[j], q, sc2);
            }
            float2 sv = unpk2(sc2);
            sc[e] = sv.x + sv.y;
        }

        // ---- batched score reduction (independent shfl chains) ----
        #pragma unroll
        for (int e = 0; e < 8; e++) {
            #pragma unroll
            for (int o = 16; o; o >>= 1)
                sc[e] += __shfl_xor_sync(0xffffffffu, sc[e], o);
        }
        if (c == 0) {
            #pragma unroll
            for (int e = 0; e < 8; e++) {
                int b = bs_sm[buf][e];
                if (b >= 0) atomicAdd(&out[1 + b], sc[e]);  // REDG, no return
            }
        }
    }

    // ---- final block reductions: hh, tt, ss ----
    #pragma unroll
    for (int o = 16; o; o >>= 1) {
        hh += __shfl_xor_sync(0xffffffffu, hh, o);
        tt += __shfl_xor_sync(0xffffffffu, tt, o);
        ss += __shfl_xor_sync(0xffffffffu, ss, o);
    }
    if (c == 0) { red2[s][0] = hh; red2[s][1] = tt; red2[s][2] = ss; }
    __syncthreads();
    if (tid == 0) {
        float HH = 0.f, TT = 0.f, SS = 0.f;
        #pragma unroll
        for (int w = 0; w < 8; w++) {
            HH += red2[w][0]; TT += red2[w][1]; SS += red2[w][2];
        }
        g_part_h2[r] = HH;
        g_part_t2[r] = TT;
        g_part_r2[r] = SS * (float)n;
    }
}

// ---------------------------------------------------------------------------
__global__ void finalize_kernel(const float* __restrict__ labels,
                                float* __restrict__ out) {
    __shared__ float sred[16 * 4];
    int tid = threadIdx.x;    // 512 threads
    float sq = 0.f;
    for (int b = tid; b < BATCH; b += 512) {
        float d = out[1 + b] - labels[b];
        sq += d * d;
    }
    float h2 = 0.f, t2 = 0.f, r2 = 0.f;
    for (int r = tid; r < REL_NUM; r += 512) {
        h2 += g_part_h2[r];
        t2 += g_part_t2[r];
        r2 += g_part_r2[r];
    }
    #pragma unroll
    for (int o = 16; o; o >>= 1) {
        sq += __shfl_xor_sync(0xffffffffu, sq, o);
        h2 += __shfl_xor_sync(0xffffffffu, h2, o);
        t2 += __shfl_xor_sync(0xffffffffu, t2, o);
        r2 += __shfl_xor_sync(0xffffffffu, r2, o);
    }
    int warp = tid >> 5, lane = tid & 31;
    if (lane == 0) {
        sred[warp * 4 + 0] = sq;
        sred[warp * 4 + 1] = h2;
        sred[warp * 4 + 2] = t2;
        sred[warp * 4 + 3] = r2;
    }
    __syncthreads();
    if (tid == 0) {
        float SQ = 0.f, H2 = 0.f, T2 = 0.f, R2 = 0.f;
        #pragma unroll
        for (int w = 0; w < 16; w++) {
            SQ += sred[w * 4 + 0];
            H2 += sred[w * 4 + 1];
            T2 += sred[w * 4 + 2];
            R2 += sred[w * 4 + 3];
        }
        float mh = H2 / ((float)BATCH * DIM);
        float mt = T2 / ((float)BATCH * DIM);
        float mr = R2 / ((float)BATCH * DIM * DIM);
        float norms = (mh + mt + mr) / 3.0f;
        out[0] = SQ / (float)BATCH + ALPHA * norms;
    }
}

// ---------------------------------------------------------------------------
extern "C" void kernel_launch(void* const* d_in, const int* in_sizes, int n_in,
                              void* d_out, int out_size) {
    const int*   h_idx  = (const int*)  d_in[0];
    const int*   r_idx  = (const int*)  d_in[1];
    const int*   t_idx  = (const int*)  d_in[2];
    const float* labels = (const float*)d_in[3];
    const float* ent_w  = (const float*)d_in[4];
    const float* rel_w  = (const float*)d_in[5];
    float* out = (float*)d_out;

    hist_kernel<<<NHBLK, 1024>>>(r_idx, out);
    scan_kernel<<<1, 512>>>();
    scatter_kernel<<<NHBLK, 1024>>>(r_idx, h_idx, t_idx);
    rescal_main_kernel<<<REL_NUM, 256>>>(ent_w, rel_w, out);
    finalize_kernel<<<1, 512>>>(labels, out);
}

// round 5
// speedup vs baseline: 1.1916x; 1.0390x over previous
#include <cuda_runtime.h>
#include <cstdint>

#define ENT_NUM 100000
#define REL_NUM 500
#define DIM     128
#define BATCH   16384
#define ALPHA   0.001f
#define NHBLK   8
#define GRP     4        // elements per group in main kernel

// ---- device scratch (no allocations allowed) ----
__device__ int   g_counts_part[NHBLK * 512];
__device__ int   g_offsets[REL_NUM + 1];
__device__ int   g_fill[512];
__device__ int   g_order[REL_NUM];
__device__ int4  g_meta[BATCH];          // (b, t_idx[b], h_idx[b], 0) grouped
__device__ float g_part_h2[REL_NUM];
__device__ float g_part_t2[REL_NUM];
__device__ float g_part_r2[REL_NUM];

// ---------------------------------------------------------------------------
// packed f32x2 + async-copy helpers (sm_100+)
// ---------------------------------------------------------------------------
typedef unsigned long long ull;
__device__ __forceinline__ ull ffma2(ull a, ull b, ull c) {
    ull d;
    asm("fma.rn.f32x2 %0, %1, %2, %3;" : "=l"(d) : "l"(a), "l"(b), "l"(c));
    return d;
}
__device__ __forceinline__ ull fmul2(ull a, ull b) {
    ull d;
    asm("mul.rn.f32x2 %0, %1, %2;" : "=l"(d) : "l"(a), "l"(b));
    return d;
}
__device__ __forceinline__ ull pk2(float x, float y) {
    ull r;
    asm("mov.b64 %0, {%1, %2};" : "=l"(r) : "f"(x), "f"(y));
    return r;
}
__device__ __forceinline__ float2 unpk2(ull v) {
    float2 r;
    asm("mov.b64 {%0, %1}, %2;" : "=f"(r.x), "=f"(r.y) : "l"(v));
    return r;
}
#define CP_ASYNC16(dst, src) \
    asm volatile("cp.async.ca.shared.global [%0], [%1], 16;" :: "r"(dst), "l"(src) : "memory")
#define CP_COMMIT()  asm volatile("cp.async.commit_group;" ::: "memory")
#define CP_WAIT1()   asm volatile("cp.async.wait_group 1;" ::: "memory")
#define CP_WAIT0()   asm volatile("cp.async.wait_group 0;" ::: "memory")

// ---------------------------------------------------------------------------
// Kernel A: privatized histogram + zero the output buffer
// ---------------------------------------------------------------------------
__global__ __launch_bounds__(1024) void hist_kernel(
    const int* __restrict__ r_idx, float* __restrict__ out)
{
    __shared__ int hist[512];
    const int tid = threadIdx.x;
    const int blk = blockIdx.x;
    if (tid < 512) hist[tid] = 0;
    __syncthreads();

    const int base = blk * 2048;
    int r0 = r_idx[base + tid];
    int r1 = r_idx[base + 1024 + tid];
    atomicAdd(&hist[r0], 1);
    atomicAdd(&hist[r1], 1);

    out[base + tid]        = 0.f;
    out[base + 1024 + tid] = 0.f;
    if (blk == 0 && tid == 0) out[BATCH] = 0.f;

    __syncthreads();
    if (tid < 512) g_counts_part[blk * 512 + tid] = hist[tid];
}

// ---------------------------------------------------------------------------
// Kernel B: sum part-counts + inclusive scan + LPT ordering (rank by count)
// ---------------------------------------------------------------------------
__global__ __launch_bounds__(512) void scan_kernel() {
    __shared__ int s[512];
    __shared__ int cnt[512];
    const int tid = threadIdx.x;
    int v = 0;
    #pragma unroll
    for (int p = 0; p < NHBLK; p++) v += g_counts_part[p * 512 + tid];
    s[tid]   = v;
    cnt[tid] = v;
    __syncthreads();
    for (int o = 1; o < 512; o <<= 1) {
        int add = (tid >= o) ? s[tid - o] : 0;
        __syncthreads();
        s[tid] += add;
        __syncthreads();
    }
    if (tid < REL_NUM) g_offsets[tid + 1] = s[tid];
    g_fill[tid] = s[tid] - v;
    if (tid == 0) g_offsets[0] = 0;

    // descending-size rank (ties broken by id) -> g_order[rank] = relation
    if (tid < REL_NUM) {
        int rank = 0;
        for (int j = 0; j < REL_NUM; j++) {
            int cj = cnt[j];
            rank += (cj > v) || (cj == v && j < tid);
        }
        g_order[rank] = tid;
    }
}

// ---------------------------------------------------------------------------
// Kernel C: scatter packed metadata (b, t_idx, h_idx) into grouped order
// ---------------------------------------------------------------------------
__global__ __launch_bounds__(1024) void scatter_kernel(
    const int* __restrict__ r_idx,
    const int* __restrict__ h_idx,
    const int* __restrict__ t_idx)
{
    const int b0 = blockIdx.x * 2048 + threadIdx.x;
    const int b1 = b0 + 1024;
    int p0 = atomicAdd(&g_fill[r_idx[b0]], 1);
    g_meta[p0] = make_int4(b0, t_idx[b0], h_idx[b0], 0);
    int p1 = atomicAdd(&g_fill[r_idx[b1]], 1);
    g_meta[p1] = make_int4(b1, t_idx[b1], h_idx[b1], 0);
}

// ---------------------------------------------------------------------------
// Main kernel: one CTA per relation (LPT order).
// Thread (s=warp, c=lane) owns R rows [16s,16s+16) x cols [4c,4c+4) in regs.
// t/h staged by cp.async (double-buffered, meta pipelined 2 groups ahead).
// Per element: 1 t-LDS.128 + 4 h-LDS.128(broadcast) + 1 hsq-LDS.32,
// 48 ffma2 + 16 pk2. Warp-partial score -> 5 shfl + REDG per warp.
// ---------------------------------------------------------------------------
__global__ __launch_bounds__(256, 2) void rescal_main_kernel(
    const float* __restrict__ ent_w,
    const float* __restrict__ rel_w,
    float*       __restrict__ out)     // out[0]=loss, out[1+b]=scores (zeroed)
{
    __shared__ __align__(16) float t_sm[2][GRP][DIM];
    __shared__ __align__(16) float h_sm[2][GRP][DIM];
    __shared__ int   bs_sm[2][GRP];
    __shared__ float red_h[8], red_s[8];
    __shared__ float red_t;

    const int tid = threadIdx.x;
    const int s   = tid >> 5;
    const int c   = tid & 31;
    const int r   = g_order[blockIdx.x];

    const uint32_t tu32 = (uint32_t)__cvta_generic_to_shared(&t_sm[0][0][0]);
    const uint32_t hu32 = (uint32_t)__cvta_generic_to_shared(&h_sm[0][0][0]);

    // ---- coalesced R load: rows 16s..16s+15, cols 4c..4c+3 ----
    const float4* Rg4 = reinterpret_cast<const float4*>(
        rel_w + (size_t)r * (DIM * DIM));
    ull Rlo[16], Rhi[16];
    float ss = 0.f;
    #pragma unroll
    for (int m = 0; m < 16; m++) {
        float4 v = Rg4[(16 * s + m) * 32 + c];
        ss += v.x * v.x + v.y * v.y + v.z * v.z + v.w * v.w;
        Rlo[m] = pk2(v.x, v.y);
        Rhi[m] = pk2(v.z, v.w);
    }

    const int start = g_offsets[r];
    const int n     = g_offsets[r + 1] - start;
    const int ngrp  = (n + GRP - 1) / GRP;
    const int e     = s & 3;           // element this warp stages
    const bool isT  = (s < 4);         // warps 0-3 stage t, 4-7 stage h

    // meta loader: broadcast LDG of int4, clamped for safety
    auto ldmeta = [&](int g) -> int4 {
        int idx = g * GRP + e;
        int pos = start + idx;
        if (pos > BATCH - 1) pos = BATCH - 1;
        return g_meta[pos];
    };
    // stager: cp.async 16B per lane (or zero-fill when past end)
    auto stage = [&](int bufn, int g, const int4& mt) {
        int idx = g * GRP + e;
        uint32_t dst = (isT ? tu32 : hu32) + (uint32_t)(bufn * GRP + e) * 512
                       + (uint32_t)c * 16;
        if (idx < n) {
            const float* src = ent_w + (size_t)(isT ? mt.y : mt.z) * DIM + c * 4;
            CP_ASYNC16(dst, src);
        } else {
            asm volatile("st.shared.v4.b32 [%0], {%1,%1,%1,%1};"
                         :: "r"(dst), "r"(0) : "memory");
        }
        if (isT && c == 0) bs_sm[bufn][e] = (idx < n) ? mt.x : -1;
    };

    // ---- pipeline prologue ----
    int4 mA = ldmeta(0);
    stage(0, 0, mA);
    CP_COMMIT();
    int4 mB = ldmeta(1);

    float hh = 0.f;
    ull   tt2 = 0ull;
    int   buf = 0;

    for (int g = 0; g < ngrp; g++, buf ^= 1) {
        __syncthreads();                    // prior readers of buf^1 done
        stage(buf ^ 1, g + 1, mB);          // stage next group
        CP_COMMIT();
        mB = ldmeta(g + 2);                 // meta 2 groups ahead
        CP_WAIT1();                         // current group data arrived
        __syncthreads();                    // publish to all warps

        #pragma unroll
        for (int ee = 0; ee < GRP; ee++) {
            const ulonglong2 t2e = *reinterpret_cast<const ulonglong2*>(
                &t_sm[buf][ee][c * 4]);                     // conflict-free
            const float4 h0 = *reinterpret_cast<const float4*>(
                &h_sm[buf][ee][16 * s]);                    // broadcast
            const float4 h1 = *reinterpret_cast<const float4*>(
                &h_sm[buf][ee][16 * s + 4]);
            const float4 h2 = *reinterpret_cast<const float4*>(
                &h_sm[buf][ee][16 * s + 8]);
            const float4 h3 = *reinterpret_cast<const float4*>(
                &h_sm[buf][ee][16 * s + 12]);
            const float hv = h_sm[buf][ee][16 * s + (c & 15)];
            hh = fmaf(hv, hv, hh);
            if (s == 0) {
                tt2 = ffma2(t2e.x, t2e.x, tt2);
                tt2 = ffma2(t2e.y, t2e.y, tt2);
            }
            ull sc2 = 0ull;
            #define ROW(m, hval) { \
                ull q = fmul2(Rlo[m], t2e.x); \
                q = ffma2(Rhi[m], t2e.y, q); \
                sc2 = ffma2(pk2(hval, hval), q, sc2); }
            ROW(0,  h0.x) ROW(1,  h0.y) ROW(2,  h0.z) ROW(3,  h0.w)
            ROW(4,  h1.x) ROW(5,  h1.y) ROW(6,  h1.z) ROW(7,  h1.w)
            ROW(8,  h2.x) ROW(9,  h2.y) ROW(10, h2.z) ROW(11, h2.w)
            ROW(12, h3.x) ROW(13, h3.y) ROW(14, h3.z) ROW(15, h3.w)
            #undef ROW

            float2 sv = unpk2(sc2);
            float sc = sv.x + sv.y;         // this warp's row-slice partial
            #pragma unroll
            for (int o = 16; o; o >>= 1)
                sc += __shfl_xor_sync(0xffffffffu, sc, o);
            if (c == 0) {
                int b = bs_sm[buf][ee];
                if (b >= 0) atomicAdd(&out[1 + b], sc);   // REDG, no return
            }
        }
    }
    CP_WAIT0();                             // drain pending copies (smem safety)

    // ---- final reductions: hh (per-warp rows, lanes x2), tt (warp0), ss ----
    float ttv = 0.f;
    if (s == 0) { float2 t2 = unpk2(tt2); ttv = t2.x + t2.y; }
    #pragma unroll
    for (int o = 16; o; o >>= 1) {
        hh  += __shfl_xor_sync(0xffffffffu, hh, o);
        ss  += __shfl_xor_sync(0xffffffffu, ss, o);
        ttv += __shfl_xor_sync(0xffffffffu, ttv, o);
    }
    if (c == 0) {
        red_h[s] = hh * 0.5f;    // lanes 0-15 and 16-31 duplicate rows
        red_s[s] = ss;
        if (s == 0) red_t = ttv;
    }
    __syncthreads();
    if (tid == 0) {
        float HH = 0.f, SS = 0.f;
        #pragma unroll
        for (int w = 0; w < 8; w++) { HH += red_h[w]; SS += red_s[w]; }
        g_part_h2[r] = HH;
        g_part_t2[r] = red_t;
        g_part_r2[r] = SS * (float)n;
    }
}

// ---------------------------------------------------------------------------
__global__ void finalize_kernel(const float* __restrict__ labels,
                                float* __restrict__ out) {
    __shared__ float sred[16 * 4];
    int tid = threadIdx.x;    // 512 threads
    float sq = 0.f;
    for (int b = tid; b < BATCH; b += 512) {
        float d = out[1 + b] - labels[b];
        sq += d * d;
    }
    float h2 = 0.f, t2 = 0.f, r2 = 0.f;
    for (int r = tid; r < REL_NUM; r += 512) {
        h2 += g_part_h2[r];
        t2 += g_part_t2[r];
        r2 += g_part_r2[r];
    }
    #pragma unroll
    for (int o = 16; o; o >>= 1) {
        sq += __shfl_xor_sync(0xffffffffu, sq, o);
        h2 += __shfl_xor_sync(0xffffffffu, h2, o);
        t2 += __shfl_xor_sync(0xffffffffu, t2, o);
        r2 += __shfl_xor_sync(0xffffffffu, r2, o);
    }
    int warp = tid >> 5, lane = tid & 31;
    if (lane == 0) {
        sred[warp * 4 + 0] = sq;
        sred[warp * 4 + 1] = h2;
        sred[warp * 4 + 2] = t2;
        sred[warp * 4 + 3] = r2;
    }
    __syncthreads();
    if (tid == 0) {
        float SQ = 0.f, H2 = 0.f, T2 = 0.f, R2 = 0.f;
        #pragma unroll
        for (int w = 0; w < 16; w++) {
            SQ += sred[w * 4 + 0];
            H2 += sred[w * 4 + 1];
            T2 += sred[w * 4 + 2];
            R2 += sred[w * 4 + 3];
        }
        float mh = H2 / ((float)BATCH * DIM);
        float mt = T2 / ((float)BATCH * DIM);
        float mr = R2 / ((float)BATCH * DIM * DIM);
        float norms = (mh + mt + mr) / 3.0f;
        out[0] = SQ / (float)BATCH + ALPHA * norms;
    }
}

// ---------------------------------------------------------------------------
extern "C" void kernel_launch(void* const* d_in, const int* in_sizes, int n_in,
                              void* d_out, int out_size) {
    const int*   h_idx  = (const int*)  d_in[0];
    const int*   r_idx  = (const int*)  d_in[1];
    const int*   t_idx  = (const int*)  d_in[2];
    const float* labels = (const float*)d_in[3];
    const float* ent_w  = (const float*)d_in[4];
    const float* rel_w  = (const float*)d_in[5];
    float* out = (float*)d_out;

    hist_kernel<<<NHBLK, 1024>>>(r_idx, out);
    scan_kernel<<<1, 512>>>();
    scatter_kernel<<<NHBLK, 1024>>>(r_idx, h_idx, t_idx);
    rescal_main_kernel<<<REL_NUM, 256>>>(ent_w, rel_w, out);
    finalize_kernel<<<1, 512>>>(labels, out);
}